// round 14
// baseline (speedup 1.0000x reference)
#include <cuda_runtime.h>
#include <cuda_fp16.h>
#include <math.h>
#include <stdint.h>

// Problem constants
#define B_  4
#define C_  64
#define HA_ 512
#define WA_ 512
#define N_  256
#define HB_ 32
#define WB_ 32
#define PLANE_ (HA_ * WA_)
#define POS_   (HB_ * WB_)
#define THREADS_ 256
#define PPT_ 4                  // positions per thread
#define CSPLIT_ 2
#define QPB_ (C_ / 4 / CSPLIT_) // 8 quads per block

#define PITCHH_ 50              // tile pitch in pixels (8B each); row stride 400B
#define MAXH_ 46                // provable bbox height bound (<=46)
#define TILE_ELEMS_ (MAXH_ * PITCHH_)   // 18.4KB/stage

// Reference float chain: grid coord -> pixel coord (monotone)
__device__ __forceinline__ float ref_chain(float g, float sz) {
    float gx = (g + 0.5f) * (2.0f / sz) - 1.0f;
    return ((gx + 1.0f) * sz - 1.0f) * 0.5f;
}

__global__ __launch_bounds__(THREADS_, 4)
void aerial_patch_sampler_kernel(const float* __restrict__ feat,
                                 const float* __restrict__ pose,
                                 float* __restrict__ out) {
    // Each pixel holds 4 channels as 2x half2 (uint2, 8B); two stages.
    __shared__ uint2 tile[2][TILE_ELEMS_];

    const int n   = blockIdx.x;
    const int b   = blockIdx.y;
    const int cz  = blockIdx.z;      // channel half (0: ch0-31, 1: ch32-63)
    const int tid = threadIdx.x;

    const float* pp = pose + ((size_t)b * N_ + n) * 3;
    const float u_off = pp[0];
    const float v_off = pp[1];
    const float theta = pp[2];
    float s, c;
    sincosf(theta, &s, &c);
    const float cos_r = c;
    const float sin_r = -s;

    // ---- bounding box of the rotated patch ----
    const float a1 = cos_r * 31.0f;
    const float a2 = -sin_r * (-16.0f), a3 = -sin_r * 15.0f;
    const float gu_min = u_off + fminf(0.0f, a1) + fminf(a2, a3);
    const float gu_max = u_off + fmaxf(0.0f, a1) + fmaxf(a2, a3);
    const float b1 = sin_r * 31.0f;
    const float b2 = cos_r * (-16.0f), b3 = cos_r * 15.0f;
    const float gv_min = v_off + fminf(0.0f, b1) + fminf(b2, b3);
    const float gv_max = v_off + fmaxf(0.0f, b1) + fmaxf(b2, b3);

    const float ixm = ref_chain(gu_min, (float)WA_);
    const float ixM = ref_chain(gu_max, (float)WA_);
    const float iym = ref_chain(gv_min, (float)HA_);
    const float iyM = ref_chain(gv_max, (float)HA_);

    int x_lo = min(max((int)floorf(ixm), 0), WA_ - 1) & ~1;   // 8B-align LDG.64
    int x_hi = min(max((int)floorf(ixM) + 1, 0), WA_ - 1);
    int y_lo = min(max((int)floorf(iym), 0), HA_ - 1);
    int y_hi = min(max((int)floorf(iyM) + 1, 0), HA_ - 1);
    if (x_hi < x_lo) x_hi = x_lo;
    if (y_hi < y_lo) y_hi = y_lo;
    const int H = min(y_hi - y_lo + 1, MAXH_);
    int x_cov_hi = min(x_hi | 1, WA_ - 1);
    if (x_cov_hi < x_lo + 1) x_cov_hi = x_lo + 1;
    const int n8 = min(((x_cov_hi - x_lo) >> 1) + 1, PITCHH_ / 2);  // 2-px granules
    const int txmax = x_cov_hi - x_lo;                               // <= 47
    const int tymax = H - 1;

    // ---- per-thread sample parameters (channel-invariant) ----
    int   pk_ab[PPT_];   // lo: o00, hi: o10
    int   pk_cd[PPT_];   // lo: o01, hi: o11
    float w00[PPT_], w10[PPT_], w01[PPT_], w11[PPT_];

    #pragma unroll
    for (int k = 0; k < PPT_; ++k) {
        const int pos = k * THREADS_ + tid;
        const int hb = pos >> 5;
        const int wb = pos & 31;

        const float gu0 = (float)(HB_ - 1 - hb);
        const float gv0 = (float)(wb - WB_ / 2);
        const float gu = u_off + cos_r * gu0 - sin_r * gv0;
        const float gv = v_off + sin_r * gu0 + cos_r * gv0;

        float gx = (gu + 0.5f) * (2.0f / (float)WA_) - 1.0f;
        float gy = (gv + 0.5f) * (2.0f / (float)HA_) - 1.0f;
        const bool valid = (fabsf(gx) < 1.0f) && (fabsf(gy) < 1.0f);
        if (!valid) { gx = 2.0f; gy = 2.0f; }

        const float ix = ((gx + 1.0f) * (float)WA_ - 1.0f) * 0.5f;
        const float iy = ((gy + 1.0f) * (float)HA_ - 1.0f) * 0.5f;

        const float x0f = floorf(ix);
        const float y0f = floorf(iy);
        const float wx1 = ix - x0f;
        const float wx0 = 1.0f - wx1;
        const float wy1 = iy - y0f;
        const float wy0 = 1.0f - wy1;

        const int x0 = (int)x0f, y0 = (int)y0f;
        const int x1 = x0 + 1,   y1 = y0 + 1;

        const bool vx0 = (x0 >= 0) && (x0 < WA_);
        const bool vx1 = (x1 >= 0) && (x1 < WA_);
        const bool vy0 = (y0 >= 0) && (y0 < HA_);
        const bool vy1 = (y1 >= 0) && (y1 < HA_);

        const int tx0 = min(max(min(max(x0, 0), WA_ - 1) - x_lo, 0), txmax);
        const int tx1 = min(max(min(max(x1, 0), WA_ - 1) - x_lo, 0), txmax);
        const int ty0 = min(max(min(max(y0, 0), HA_ - 1) - y_lo, 0), tymax);
        const int ty1 = min(max(min(max(y1, 0), HA_ - 1) - y_lo, 0), tymax);

        pk_ab[k] = (ty0 * PITCHH_ + tx0) | ((ty0 * PITCHH_ + tx1) << 16);
        pk_cd[k] = (ty1 * PITCHH_ + tx0) | ((ty1 * PITCHH_ + tx1) << 16);

        w00[k] = (vx0 && vy0) ? (wx0 * wy0) : 0.0f;
        w10[k] = (vx1 && vy0) ? (wx1 * wy0) : 0.0f;
        w01[k] = (vx0 && vy1) ? (wx0 * wy1) : 0.0f;
        w11[k] = (vx1 && vy1) ? (wx1 * wy1) : 0.0f;
    }

    // This block handles channels [cz*32, cz*32+32)
    const int ch0 = cz * (C_ / CSPLIT_);
    const float* plane0 = feat + ((size_t)b * C_ + ch0) * PLANE_
                               + (size_t)y_lo * WA_ + x_lo;
    float* outp = out + (((size_t)b * N_ + n) * C_ + ch0) * (size_t)POS_;

    const int lane = tid & 31;   // 2-px granule column
    const int wrp  = tid >> 5;   // starting row, stride 8
    const bool ld_act = (lane < n8);
    const size_t goff = 2 * lane;

    // Two-row loader chunk state (rows ra = wrp+16c, rb = ra+8)
    float2 va[4], vb[4];

    auto ldg_chunk = [&](const float* sq, int cidx) {
        const int ra = wrp + 16 * cidx;
        const int rb = ra + 8;
        if (ld_act && ra < H) {
            const float* p = sq + (size_t)ra * WA_ + goff;
            va[0] = *reinterpret_cast<const float2*>(p);
            va[1] = *reinterpret_cast<const float2*>(p + PLANE_);
            va[2] = *reinterpret_cast<const float2*>(p + 2 * (size_t)PLANE_);
            va[3] = *reinterpret_cast<const float2*>(p + 3 * (size_t)PLANE_);
        }
        if (ld_act && rb < H) {
            const float* p = sq + (size_t)rb * WA_ + goff;
            vb[0] = *reinterpret_cast<const float2*>(p);
            vb[1] = *reinterpret_cast<const float2*>(p + PLANE_);
            vb[2] = *reinterpret_cast<const float2*>(p + 2 * (size_t)PLANE_);
            vb[3] = *reinterpret_cast<const float2*>(p + 3 * (size_t)PLANE_);
        }
    };

    auto sts_chunk = [&](uint2* dst, int cidx) {
        const int ra = wrp + 16 * cidx;
        const int rb = ra + 8;
        if (ld_act && ra < H) {
            __half2 p0lo = __floats2half2_rn(va[0].x, va[1].x);
            __half2 p0hi = __floats2half2_rn(va[2].x, va[3].x);
            __half2 p1lo = __floats2half2_rn(va[0].y, va[1].y);
            __half2 p1hi = __floats2half2_rn(va[2].y, va[3].y);
            uint4 pk;
            pk.x = *reinterpret_cast<unsigned*>(&p0lo);
            pk.y = *reinterpret_cast<unsigned*>(&p0hi);
            pk.z = *reinterpret_cast<unsigned*>(&p1lo);
            pk.w = *reinterpret_cast<unsigned*>(&p1hi);
            *reinterpret_cast<uint4*>(&dst[ra * PITCHH_ + 2 * lane]) = pk;
        }
        if (ld_act && rb < H) {
            __half2 p0lo = __floats2half2_rn(vb[0].x, vb[1].x);
            __half2 p0hi = __floats2half2_rn(vb[2].x, vb[3].x);
            __half2 p1lo = __floats2half2_rn(vb[0].y, vb[1].y);
            __half2 p1hi = __floats2half2_rn(vb[2].y, vb[3].y);
            uint4 pk;
            pk.x = *reinterpret_cast<unsigned*>(&p0lo);
            pk.y = *reinterpret_cast<unsigned*>(&p0hi);
            pk.z = *reinterpret_cast<unsigned*>(&p1lo);
            pk.w = *reinterpret_cast<unsigned*>(&p1hi);
            *reinterpret_cast<uint4*>(&dst[rb * PITCHH_ + 2 * lane]) = pk;
        }
    };

    auto sample_k = [&](const uint2* tb, float* out0, int k) {
        const int o00 = pk_ab[k] & 0xffff;
        const int o10 = (pk_ab[k] >> 16) & 0xffff;
        const int o01 = pk_cd[k] & 0xffff;
        const int o11 = (pk_cd[k] >> 16) & 0xffff;

        const uint2 t00 = tb[o00];
        const uint2 t10 = tb[o10];
        const uint2 t01 = tb[o01];
        const uint2 t11 = tb[o11];

        const float2 a00 = __half22float2(*reinterpret_cast<const __half2*>(&t00.x));
        const float2 c00 = __half22float2(*reinterpret_cast<const __half2*>(&t00.y));
        const float2 a10 = __half22float2(*reinterpret_cast<const __half2*>(&t10.x));
        const float2 c10 = __half22float2(*reinterpret_cast<const __half2*>(&t10.y));
        const float2 a01 = __half22float2(*reinterpret_cast<const __half2*>(&t01.x));
        const float2 c01 = __half22float2(*reinterpret_cast<const __half2*>(&t01.y));
        const float2 a11 = __half22float2(*reinterpret_cast<const __half2*>(&t11.x));
        const float2 c11 = __half22float2(*reinterpret_cast<const __half2*>(&t11.y));

        const float r0 = fmaf(a00.x, w00[k], fmaf(a10.x, w10[k],
                         fmaf(a01.x, w01[k], a11.x * w11[k])));
        const float r1 = fmaf(a00.y, w00[k], fmaf(a10.y, w10[k],
                         fmaf(a01.y, w01[k], a11.y * w11[k])));
        const float r2 = fmaf(c00.x, w00[k], fmaf(c10.x, w10[k],
                         fmaf(c01.x, w01[k], c11.x * w11[k])));
        const float r3 = fmaf(c00.y, w00[k], fmaf(c10.y, w10[k],
                         fmaf(c01.y, w01[k], c11.y * w11[k])));

        const int oi = k * THREADS_ + tid;
        out0[oi] = r0;
        out0[oi + POS_] = r1;
        out0[oi + 2 * POS_] = r2;
        out0[oi + 3 * POS_] = r3;
    };

    // ---- prologue: quad 0 -> stage 0; then pre-issue quad 1 chunk 0 LDGs ----
    {
        const float* sq = plane0;
        #pragma unroll
        for (int cidx = 0; cidx < 3; ++cidx) {
            ldg_chunk(sq, cidx);
            sts_chunk(tile[0], cidx);
        }
    }
    if (QPB_ > 1) ldg_chunk(plane0 + 4 * (size_t)PLANE_, 0);  // hoisted over barrier
    __syncthreads();

    for (int q = 0; q < QPB_; ++q) {
        const uint2* tb = tile[q & 1];
        uint2* nxt = tile[(q + 1) & 1];
        float* out0 = outp + (size_t)(4 * q) * POS_;
        const bool pf  = (q + 1 < QPB_);
        const bool pf2 = (q + 2 < QPB_);
        const float* sq  = plane0 + (size_t)(4 * (q + 1)) * PLANE_;
        const float* sq2 = plane0 + (size_t)(4 * (q + 2)) * PLANE_;

        // chunk 0 of quad q+1 was LDG'd BEFORE the barrier (regs survive it):
        // its latency overlapped barrier convergence. Store it, then pipeline.
        sample_k(tb, out0, 0);
        if (pf) { sts_chunk(nxt, 0); ldg_chunk(sq, 1); }
        sample_k(tb, out0, 1);
        if (pf) { sts_chunk(nxt, 1); ldg_chunk(sq, 2); }
        sample_k(tb, out0, 2);
        if (pf) sts_chunk(nxt, 2);
        sample_k(tb, out0, 3);
        if (pf2) ldg_chunk(sq2, 0);   // hoist next iteration's chunk 0 over the barrier

        __syncthreads();
    }
}

extern "C" void kernel_launch(void* const* d_in, const int* in_sizes, int n_in,
                              void* d_out, int out_size) {
    const float* aer_feat = (const float*)d_in[0];
    const float* pose_uvr = (const float*)d_in[1];
    float* out = (float*)d_out;

    dim3 grid(N_, B_, CSPLIT_);
    dim3 block(THREADS_);
    aerial_patch_sampler_kernel<<<grid, block>>>(aer_feat, pose_uvr, out);
}

// round 16
// speedup vs baseline: 1.3456x; 1.3456x over previous
#include <cuda_runtime.h>
#include <cuda_fp16.h>
#include <math.h>
#include <stdint.h>

// Problem constants
#define B_  4
#define C_  64
#define HA_ 512
#define WA_ 512
#define N_  256
#define HB_ 32
#define WB_ 32
#define PLANE_ (HA_ * WA_)
#define POS_   (HB_ * WB_)
#define THREADS_ 256
#define PPT_ 4                  // positions per thread
#define CSPLIT_ 2
#define QPB_ (C_ / 4 / CSPLIT_) // 8 quads per block

#define PITCHH_ 66              // tile pitch in pixels (8B each); row stride 528B
#define MAXH_ 46                // provable bbox height bound (<=46)
#define TILE_ELEMS_ (MAXH_ * PITCHH_)

// Reference float chain: grid coord -> pixel coord (monotone)
__device__ __forceinline__ float ref_chain(float g, float sz) {
    float gx = (g + 0.5f) * (2.0f / sz) - 1.0f;
    return ((gx + 1.0f) * sz - 1.0f) * 0.5f;
}

__global__ __launch_bounds__(THREADS_, 4)
void aerial_patch_sampler_kernel(const float* __restrict__ feat,
                                 const float* __restrict__ pose,
                                 float* __restrict__ out) {
    // Each pixel holds 4 channels as 2x half2 (uint2, 8B); two stages.
    __shared__ uint2 tile[2][TILE_ELEMS_];

    const int n   = blockIdx.x;
    const int b   = blockIdx.y;
    const int cz  = blockIdx.z;      // channel half (0: ch0-31, 1: ch32-63)
    const int tid = threadIdx.x;

    const float* pp = pose + ((size_t)b * N_ + n) * 3;
    const float u_off = pp[0];
    const float v_off = pp[1];
    const float theta = pp[2];
    float s, c;
    sincosf(theta, &s, &c);
    const float cos_r = c;
    const float sin_r = -s;

    // ---- bounding box of the rotated patch ----
    const float a1 = cos_r * 31.0f;
    const float a2 = -sin_r * (-16.0f), a3 = -sin_r * 15.0f;
    const float gu_min = u_off + fminf(0.0f, a1) + fminf(a2, a3);
    const float gu_max = u_off + fmaxf(0.0f, a1) + fmaxf(a2, a3);
    const float b1 = sin_r * 31.0f;
    const float b2 = cos_r * (-16.0f), b3 = cos_r * 15.0f;
    const float gv_min = v_off + fminf(0.0f, b1) + fminf(b2, b3);
    const float gv_max = v_off + fmaxf(0.0f, b1) + fmaxf(b2, b3);

    const float ixm = ref_chain(gu_min, (float)WA_);
    const float ixM = ref_chain(gu_max, (float)WA_);
    const float iym = ref_chain(gv_min, (float)HA_);
    const float iyM = ref_chain(gv_max, (float)HA_);

    int x_lo = min(max((int)floorf(ixm), 0), WA_ - 1) & ~1;   // 8B-align LDG.64
    int x_hi = min(max((int)floorf(ixM) + 1, 0), WA_ - 1);
    int y_lo = min(max((int)floorf(iym), 0), HA_ - 1);
    int y_hi = min(max((int)floorf(iyM) + 1, 0), HA_ - 1);
    if (x_hi < x_lo) x_hi = x_lo;
    if (y_hi < y_lo) y_hi = y_lo;
    const int H = min(y_hi - y_lo + 1, MAXH_);
    int x_cov_hi = min(x_hi | 1, WA_ - 1);
    if (x_cov_hi < x_lo + 1) x_cov_hi = x_lo + 1;
    const int n8 = min(((x_cov_hi - x_lo) >> 1) + 1, 32);     // 2-px granules (<=24)
    const int txmax = x_cov_hi - x_lo;
    const int tymax = H - 1;

    // ---- per-thread sample parameters (channel-invariant) ----
    int   pk_ab[PPT_];   // lo: o00, hi: o10
    int   pk_cd[PPT_];   // lo: o01, hi: o11
    float w00[PPT_], w10[PPT_], w01[PPT_], w11[PPT_];

    #pragma unroll
    for (int k = 0; k < PPT_; ++k) {
        const int pos = k * THREADS_ + tid;
        const int hb = pos >> 5;
        const int wb = pos & 31;

        const float gu0 = (float)(HB_ - 1 - hb);
        const float gv0 = (float)(wb - WB_ / 2);
        const float gu = u_off + cos_r * gu0 - sin_r * gv0;
        const float gv = v_off + sin_r * gu0 + cos_r * gv0;

        float gx = (gu + 0.5f) * (2.0f / (float)WA_) - 1.0f;
        float gy = (gv + 0.5f) * (2.0f / (float)HA_) - 1.0f;
        const bool valid = (fabsf(gx) < 1.0f) && (fabsf(gy) < 1.0f);
        if (!valid) { gx = 2.0f; gy = 2.0f; }

        const float ix = ((gx + 1.0f) * (float)WA_ - 1.0f) * 0.5f;
        const float iy = ((gy + 1.0f) * (float)HA_ - 1.0f) * 0.5f;

        const float x0f = floorf(ix);
        const float y0f = floorf(iy);
        const float wx1 = ix - x0f;
        const float wx0 = 1.0f - wx1;
        const float wy1 = iy - y0f;
        const float wy0 = 1.0f - wy1;

        const int x0 = (int)x0f, y0 = (int)y0f;
        const int x1 = x0 + 1,   y1 = y0 + 1;

        const bool vx0 = (x0 >= 0) && (x0 < WA_);
        const bool vx1 = (x1 >= 0) && (x1 < WA_);
        const bool vy0 = (y0 >= 0) && (y0 < HA_);
        const bool vy1 = (y1 >= 0) && (y1 < HA_);

        const int tx0 = min(max(min(max(x0, 0), WA_ - 1) - x_lo, 0), txmax);
        const int tx1 = min(max(min(max(x1, 0), WA_ - 1) - x_lo, 0), txmax);
        const int ty0 = min(max(min(max(y0, 0), HA_ - 1) - y_lo, 0), tymax);
        const int ty1 = min(max(min(max(y1, 0), HA_ - 1) - y_lo, 0), tymax);

        pk_ab[k] = (ty0 * PITCHH_ + tx0) | ((ty0 * PITCHH_ + tx1) << 16);
        pk_cd[k] = (ty1 * PITCHH_ + tx0) | ((ty1 * PITCHH_ + tx1) << 16);

        w00[k] = (vx0 && vy0) ? (wx0 * wy0) : 0.0f;
        w10[k] = (vx1 && vy0) ? (wx1 * wy0) : 0.0f;
        w01[k] = (vx0 && vy1) ? (wx0 * wy1) : 0.0f;
        w11[k] = (vx1 && vy1) ? (wx1 * wy1) : 0.0f;
    }

    // This block handles channels [cz*32, cz*32+32)
    const int ch0 = cz * (C_ / CSPLIT_);
    const float* plane0 = feat + ((size_t)b * C_ + ch0) * PLANE_
                               + (size_t)y_lo * WA_ + x_lo;
    float* outp = out + (((size_t)b * N_ + n) * C_ + ch0) * (size_t)POS_;

    const int lane = tid & 31;   // 2-px granule column
    const int wrp  = tid >> 5;   // starting row, stride 8
    const bool ld_act = (lane < n8);
    const size_t goff = 2 * lane;

    // Two-row loader chunk state (rows ra = wrp+16c, rb = ra+8)
    float2 va[4], vb[4];

    auto ldg_chunk = [&](const float* sq, int cidx) {
        const int ra = wrp + 16 * cidx;
        const int rb = ra + 8;
        if (ld_act && ra < H) {
            const float* p = sq + (size_t)ra * WA_ + goff;
            va[0] = *reinterpret_cast<const float2*>(p);
            va[1] = *reinterpret_cast<const float2*>(p + PLANE_);
            va[2] = *reinterpret_cast<const float2*>(p + 2 * (size_t)PLANE_);
            va[3] = *reinterpret_cast<const float2*>(p + 3 * (size_t)PLANE_);
        }
        if (ld_act && rb < H) {
            const float* p = sq + (size_t)rb * WA_ + goff;
            vb[0] = *reinterpret_cast<const float2*>(p);
            vb[1] = *reinterpret_cast<const float2*>(p + PLANE_);
            vb[2] = *reinterpret_cast<const float2*>(p + 2 * (size_t)PLANE_);
            vb[3] = *reinterpret_cast<const float2*>(p + 3 * (size_t)PLANE_);
        }
    };

    auto sts_chunk = [&](uint2* dst, int cidx) {
        const int ra = wrp + 16 * cidx;
        const int rb = ra + 8;
        if (ld_act && ra < H) {
            __half2 p0lo = __floats2half2_rn(va[0].x, va[1].x);
            __half2 p0hi = __floats2half2_rn(va[2].x, va[3].x);
            __half2 p1lo = __floats2half2_rn(va[0].y, va[1].y);
            __half2 p1hi = __floats2half2_rn(va[2].y, va[3].y);
            uint4 pk;
            pk.x = *reinterpret_cast<unsigned*>(&p0lo);
            pk.y = *reinterpret_cast<unsigned*>(&p0hi);
            pk.z = *reinterpret_cast<unsigned*>(&p1lo);
            pk.w = *reinterpret_cast<unsigned*>(&p1hi);
            *reinterpret_cast<uint4*>(&dst[ra * PITCHH_ + 2 * lane]) = pk;
        }
        if (ld_act && rb < H) {
            __half2 p0lo = __floats2half2_rn(vb[0].x, vb[1].x);
            __half2 p0hi = __floats2half2_rn(vb[2].x, vb[3].x);
            __half2 p1lo = __floats2half2_rn(vb[0].y, vb[1].y);
            __half2 p1hi = __floats2half2_rn(vb[2].y, vb[3].y);
            uint4 pk;
            pk.x = *reinterpret_cast<unsigned*>(&p0lo);
            pk.y = *reinterpret_cast<unsigned*>(&p0hi);
            pk.z = *reinterpret_cast<unsigned*>(&p1lo);
            pk.w = *reinterpret_cast<unsigned*>(&p1hi);
            *reinterpret_cast<uint4*>(&dst[rb * PITCHH_ + 2 * lane]) = pk;
        }
    };

    auto sample_k = [&](const uint2* tb, float* out0, int k) {
        const int o00 = pk_ab[k] & 0xffff;
        const int o10 = (pk_ab[k] >> 16) & 0xffff;
        const int o01 = pk_cd[k] & 0xffff;
        const int o11 = (pk_cd[k] >> 16) & 0xffff;

        const uint2 t00 = tb[o00];
        const uint2 t10 = tb[o10];
        const uint2 t01 = tb[o01];
        const uint2 t11 = tb[o11];

        const float2 a00 = __half22float2(*reinterpret_cast<const __half2*>(&t00.x));
        const float2 c00 = __half22float2(*reinterpret_cast<const __half2*>(&t00.y));
        const float2 a10 = __half22float2(*reinterpret_cast<const __half2*>(&t10.x));
        const float2 c10 = __half22float2(*reinterpret_cast<const __half2*>(&t10.y));
        const float2 a01 = __half22float2(*reinterpret_cast<const __half2*>(&t01.x));
        const float2 c01 = __half22float2(*reinterpret_cast<const __half2*>(&t01.y));
        const float2 a11 = __half22float2(*reinterpret_cast<const __half2*>(&t11.x));
        const float2 c11 = __half22float2(*reinterpret_cast<const __half2*>(&t11.y));

        const float r0 = fmaf(a00.x, w00[k], fmaf(a10.x, w10[k],
                         fmaf(a01.x, w01[k], a11.x * w11[k])));
        const float r1 = fmaf(a00.y, w00[k], fmaf(a10.y, w10[k],
                         fmaf(a01.y, w01[k], a11.y * w11[k])));
        const float r2 = fmaf(c00.x, w00[k], fmaf(c10.x, w10[k],
                         fmaf(c01.x, w01[k], c11.x * w11[k])));
        const float r3 = fmaf(c00.y, w00[k], fmaf(c10.y, w10[k],
                         fmaf(c01.y, w01[k], c11.y * w11[k])));

        const int oi = k * THREADS_ + tid;
        out0[oi] = r0;
        out0[oi + POS_] = r1;
        out0[oi + 2 * POS_] = r2;
        out0[oi + 3 * POS_] = r3;
    };

    // ---- prologue: first quad -> stage 0 ----
    {
        const float* sq = plane0;
        #pragma unroll
        for (int cidx = 0; cidx < 3; ++cidx) {
            ldg_chunk(sq, cidx);
            sts_chunk(tile[0], cidx);
        }
    }
    __syncthreads();

    for (int q = 0; q < QPB_; ++q) {
        const uint2* tb = tile[q & 1];
        uint2* nxt = tile[(q + 1) & 1];
        float* out0 = outp + (size_t)(4 * q) * POS_;
        const bool pf = (q + 1 < QPB_);
        const float* sq = plane0 + (size_t)(4 * (q + 1)) * PLANE_;

        // pipelined: LDG chunk -> sample (hide latency) -> STS chunk -> next LDG
        if (pf) ldg_chunk(sq, 0);
        sample_k(tb, out0, 0);
        if (pf) { sts_chunk(nxt, 0); ldg_chunk(sq, 1); }
        sample_k(tb, out0, 1);
        if (pf) { sts_chunk(nxt, 1); ldg_chunk(sq, 2); }
        sample_k(tb, out0, 2);
        sample_k(tb, out0, 3);          // moved up: hides chunk-2 LDG latency
        if (pf) sts_chunk(nxt, 2);      // STS after both samples (no live-range growth)

        __syncthreads();
    }
}

extern "C" void kernel_launch(void* const* d_in, const int* in_sizes, int n_in,
                              void* d_out, int out_size) {
    const float* aer_feat = (const float*)d_in[0];
    const float* pose_uvr = (const float*)d_in[1];
    float* out = (float*)d_out;

    dim3 grid(N_, B_, CSPLIT_);
    dim3 block(THREADS_);
    aerial_patch_sampler_kernel<<<grid, block>>>(aer_feat, pose_uvr, out);
}